// round 15
// baseline (speedup 1.0000x reference)
#include <cuda_runtime.h>
#include <cuda_fp16.h>
#include <math.h>
#include <stdint.h>

#define B_  2
#define T_  2048
#define D_  1024
#define H_  16
#define DH_ 64
#define QKV_COLS 3072   // 3*D
#define BT_ (B_*T_)     // 4096

// Scratch (allocation-free rule: __device__ globals)
__device__ __half g_xh[(size_t)BT_ * D_];            // 8 MB
__device__ __half g_wqkvh[(size_t)QKV_COLS * D_];    // 6 MB
__device__ __half g_wprojh[(size_t)D_ * D_];         // 2 MB
__device__ __half g_yh[(size_t)BT_ * D_];            // 8 MB
__device__ __half g_qkvh[(size_t)BT_ * QKV_COLS];    // 24 MB (rope applied, q scaled)

// ---------------------------------------------------------------------------
// Helpers
// ---------------------------------------------------------------------------
__device__ __forceinline__ float ex2f(float x) {
    float r;
    asm("ex2.approx.f32 %0, %1;" : "=f"(r) : "f"(x));
    return r;
}
__device__ __forceinline__ uint32_t h2ex2(uint32_t x) {
    uint32_t r;
    asm("ex2.approx.f16x2 %0, %1;" : "=r"(r) : "r"(x));
    return r;
}
__device__ __forceinline__ void mma_f16(float* c, const uint32_t* a, const uint32_t* b) {
    asm volatile(
        "mma.sync.aligned.m16n8k16.row.col.f32.f16.f16.f32 "
        "{%0,%1,%2,%3}, {%4,%5,%6,%7}, {%8,%9}, {%0,%1,%2,%3};"
        : "+f"(c[0]), "+f"(c[1]), "+f"(c[2]), "+f"(c[3])
        : "r"(a[0]), "r"(a[1]), "r"(a[2]), "r"(a[3]), "r"(b[0]), "r"(b[1]));
}
__device__ __forceinline__ void ldsm_x4(uint32_t addr, uint32_t* r) {
    asm volatile("ldmatrix.sync.aligned.m8n8.x4.shared.b16 {%0,%1,%2,%3}, [%4];"
                 : "=r"(r[0]), "=r"(r[1]), "=r"(r[2]), "=r"(r[3]) : "r"(addr));
}
__device__ __forceinline__ void ldsm_x4t(uint32_t addr, uint32_t* r) {
    asm volatile("ldmatrix.sync.aligned.m8n8.x4.trans.shared.b16 {%0,%1,%2,%3}, [%4];"
                 : "=r"(r[0]), "=r"(r[1]), "=r"(r[2]), "=r"(r[3]) : "r"(addr));
}
__device__ __forceinline__ void cpa16(void* smem, const void* g) {
    uint32_t s = (uint32_t)__cvta_generic_to_shared(smem);
    asm volatile("cp.async.cg.shared.global [%0], [%1], 16;" :: "r"(s), "l"(g));
}
#define CP_COMMIT() asm volatile("cp.async.commit_group;")
#define CP_WAIT(n)  asm volatile("cp.async.wait_group %0;" :: "n"(n))

// ---------------------------------------------------------------------------
// Merged fp16 rounding pre-pass (x, Wqkv, Wproj in one launch)
// ---------------------------------------------------------------------------
#define N1H (BT_*D_/2)
#define N2H (QKV_COLS*D_/2)
#define N3H (D_*D_/2)
__global__ void round3_kernel(const float* __restrict__ x, __half* __restrict__ xh,
                              const float* __restrict__ wq, __half* __restrict__ wqh,
                              const float* __restrict__ wp, __half* __restrict__ wph) {
    int i = blockIdx.x * blockDim.x + threadIdx.x;
    if (i < N1H) {
        float2 v = ((const float2*)x)[i];
        ((__half2*)xh)[i] = __floats2half2_rn(v.x, v.y);
    } else if (i < N1H + N2H) {
        int j = i - N1H;
        float2 v = ((const float2*)wq)[j];
        ((__half2*)wqh)[j] = __floats2half2_rn(v.x, v.y);
    } else if (i < N1H + N2H + N3H) {
        int j = i - N1H - N2H;
        float2 v = ((const float2*)wp)[j];
        ((__half2*)wph)[j] = __floats2half2_rn(v.x, v.y);
    }
}

// ---------------------------------------------------------------------------
// fp16 tensor-core GEMM (NT): 4 warps (2x2), warp tile 64x64, CTA 128x128,
// BK=32 halves, 4-stage cp.async ring, ldmatrix frags, m16n8k16 mma.
// EPI=0: C = acc + bias (fp32).
// EPI=1: fused rope -> fp16 qkvh in GEMM-natural layout (coalesced stores).
// ---------------------------------------------------------------------------
#define GSH 40                 // smem row stride in halves (32 + 8 pad)
#define STGH (2*128*GSH)       // halves per stage (A tile + B tile)
#define NSTG 4

template <int EPI>
__global__ __launch_bounds__(128, 2)
void gemm_f16(const __half* __restrict__ A, const __half* __restrict__ W,
              const float* __restrict__ bias, float* __restrict__ C,
              __half* __restrict__ Ch, int M, int N, int K) {
    extern __shared__ __half hsm[];

    int tid = threadIdx.x, lane = tid & 31, wid = tid >> 5;
    int g = lane >> 2, t = lane & 3;
    int wm = wid >> 1, wn = wid & 1;
    int m0 = blockIdx.y * 128, n0 = blockIdx.x * 128;

    int lr = lane & 7, sel = lane >> 3;
    int aRow = lr + (sel & 1) * 8, aColH = (sel >> 1) * 8;
    int bRow = lr + (sel >> 1) * 8, bColH = (sel & 1) * 8;

    uint32_t smBase = (uint32_t)__cvta_generic_to_shared(hsm);

    float acc[4][8][4];
#pragma unroll
    for (int i = 0; i < 4; i++)
#pragma unroll
        for (int j = 0; j < 8; j++)
#pragma unroll
            for (int e = 0; e < 4; e++) acc[i][j][e] = 0.f;

    const int nk = K / 32;

    auto loadStage = [&](int st, int kt) {
        __half* as = hsm + st * STGH;
        __half* bs = as + 128 * GSH;
        int k0 = kt * 32;
#pragma unroll
        for (int p = 0; p < 4; p++) {
            int idx = tid + p * 128;
            int row = idx >> 2, c8 = (idx & 3) * 8;
            cpa16(as + row * GSH + c8, A + (size_t)(m0 + row) * K + k0 + c8);
            cpa16(bs + row * GSH + c8, W + (size_t)(n0 + row) * K + k0 + c8);
        }
        CP_COMMIT();
    };

    loadStage(0, 0);
    loadStage(1, 1);
    loadStage(2, 2);

    for (int kt = 0; kt < nk; kt++) {
        int rem = nk - kt;
        if (rem > 2) { CP_WAIT(2); } else if (rem == 2) { CP_WAIT(1); } else { CP_WAIT(0); }
        __syncthreads();
        if (kt + 3 < nk) loadStage((kt + 3) & (NSTG - 1), kt + 3);

        int st = kt & (NSTG - 1);
        uint32_t aB = smBase + (uint32_t)(st * STGH) * 2u;
        uint32_t bB = aB + (uint32_t)(128 * GSH) * 2u;
#pragma unroll
        for (int kk = 0; kk < 2; kk++) {
            uint32_t af[4][4], bf[8][2];
#pragma unroll
            for (int mf = 0; mf < 4; mf++)
                ldsm_x4(aB + ((wm * 64 + mf * 16 + aRow) * GSH + kk * 16 + aColH) * 2u, af[mf]);
#pragma unroll
            for (int nfp = 0; nfp < 4; nfp++) {
                uint32_t r4[4];
                ldsm_x4(bB + ((wn * 64 + nfp * 16 + bRow) * GSH + kk * 16 + bColH) * 2u, r4);
                bf[2 * nfp][0] = r4[0]; bf[2 * nfp][1] = r4[1];
                bf[2 * nfp + 1][0] = r4[2]; bf[2 * nfp + 1][1] = r4[3];
            }
#pragma unroll
            for (int mf = 0; mf < 4; mf++)
#pragma unroll
                for (int nf = 0; nf < 8; nf++)
                    mma_f16(acc[mf][nf], af[mf], bf[nf]);
        }
    }

    if (EPI == 0) {
#pragma unroll
        for (int mf = 0; mf < 4; mf++) {
            int r0 = m0 + wm * 64 + mf * 16 + g;
            int r1 = r0 + 8;
#pragma unroll
            for (int nf = 0; nf < 8; nf++) {
                int c = n0 + wn * 64 + nf * 8 + 2 * t;
                float bx = bias[c], by = bias[c + 1];
                float2 v0 = make_float2(acc[mf][nf][0] + bx, acc[mf][nf][1] + by);
                float2 v1 = make_float2(acc[mf][nf][2] + bx, acc[mf][nf][3] + by);
                *(float2*)(C + (size_t)r0 * N + c) = v0;
                *(float2*)(C + (size_t)r1 * N + c) = v1;
            }
        }
    } else {
        const float QSC = 0.125f * 1.44269504f;
        const float L2_10K = 13.2877123795f;
        int sub[8];
        float invf[8], bx[8], by[8];
#pragma unroll
        for (int nf = 0; nf < 8; nf++) {
            int n = n0 + wn * 64 + nf * 8 + 2 * t;
            int r = n % 192;
            sub[nf] = r >> 6;
            int d = r & 63;
            invf[nf] = ex2f(-((float)(d & ~1) / 64.f) * L2_10K);
            bx[nf] = bias[n];
            by[nf] = bias[n + 1];
        }
#pragma unroll
        for (int mf = 0; mf < 4; mf++) {
#pragma unroll
            for (int hr = 0; hr < 2; hr++) {
                int row = m0 + wm * 64 + mf * 16 + g + hr * 8;
                int tpos = row & (T_ - 1);
                float ftp = (float)tpos;
                __half* crow = Ch + (size_t)row * N;
#pragma unroll
                for (int nf = 0; nf < 8; nf++) {
                    int c = n0 + wn * 64 + nf * 8 + 2 * t;
                    float e = acc[mf][nf][hr * 2]     + bx[nf];
                    float o = acc[mf][nf][hr * 2 + 1] + by[nf];
                    if (sub[nf] == 2) {
                        *(__half2*)(crow + c) = __floats2half2_rn(e, o);
                    } else {
                        float sn, cs;
                        __sincosf(ftp * invf[nf], &sn, &cs);
                        float re = e * cs - o * (1.f - cs);
                        float ro = o * sn + e * (1.f - sn);
                        if (sub[nf] == 0) { re *= QSC; ro *= QSC; }
                        *(__half2*)(crow + c) = __floats2half2_rn(re, ro);
                    }
                }
            }
        }
    }
}

// ---------------------------------------------------------------------------
// Flash attention, fp16 mma. Br=64, 128 threads (4 warps), occupancy 4.
// R15: diagonal-tile block skipping — in the tile containing the diagonal,
// warp wid only computes nfp/kf blocks 0..wid (rest fully masked: S blocks
// set to -inf, their P exactly 0, PV/lacc blocks skipped entirely).
// ---------------------------------------------------------------------------
#define HST 72   // half-stride per smem row (64 + 8 pad)
#define MT_ 64   // query rows per CTA

__global__ __launch_bounds__(128, 4)
void attn_f16_kernel(const __half* __restrict__ qkv, __half* __restrict__ yh) {
    int bh = blockIdx.y;
    int b = bh >> 4, h = bh & 15;
    int it = gridDim.x - 1 - blockIdx.x;   // heaviest tiles first
    int m0 = it * MT_;
    int tid = threadIdx.x, lane = tid & 31, wid = tid >> 5;
    int g = lane >> 2, t = lane & 3;

    extern __shared__ __half hsm[];
    __half* Qs = hsm;                    // [64][HST]
    __half* Ks = hsm + MT_ * HST;        // [2][64][HST]
    __half* Vs = Ks + 2 * 64 * HST;      // [2][64][HST]
    uint32_t qsB = (uint32_t)__cvta_generic_to_shared(Qs);
    uint32_t ksB = (uint32_t)__cvta_generic_to_shared(Ks);
    uint32_t vsB = (uint32_t)__cvta_generic_to_shared(Vs);

    int lr = lane & 7, sel = lane >> 3;
    int aRow = lr + (sel & 1) * 8, aColH = (sel >> 1) * 8;
    int bRow = lr + (sel >> 1) * 8, bColH = (sel & 1) * 8;
    int vRow = lr + (sel & 1) * 8, vColH = (sel >> 1) * 8;

    // base of this (b, h): row stride QKV_COLS; q at +0, k at +64, v at +128
    const __half* base = qkv + (size_t)(b * T_) * QKV_COLS + h * 192;

    // Q tile: 64 rows x 8 chunks = 512 chunks, 128 threads -> 4 each
#pragma unroll
    for (int p = 0; p < 4; p++) {
        int j = tid + p * 128;
        int row = j >> 3, c8 = (j & 7) * 8;
        cpa16(Qs + row * HST + c8, base + (size_t)(m0 + row) * QKV_COLS + c8);
    }
    auto loadTile = [&](int buf, int s0) {
#pragma unroll
        for (int p = 0; p < 4; p++) {
            int j = tid + p * 128;
            int row = j >> 3, c8 = (j & 7) * 8;
            const __half* src = base + (size_t)(s0 + row) * QKV_COLS;
            cpa16(Ks + buf * 64 * HST + row * HST + c8, src + 64 + c8);
            cpa16(Vs + buf * 64 * HST + row * HST + c8, src + 128 + c8);
        }
    };
    loadTile(0, 0);
    CP_COMMIT();
    CP_WAIT(0);
    __syncthreads();

    uint32_t qf[4][4];
#pragma unroll
    for (int kf = 0; kf < 4; kf++)
        ldsm_x4(qsB + ((wid * 16 + aRow) * HST + kf * 16 + aColH) * 2u, qf[kf]);

    float o[8][4];
#pragma unroll
    for (int nf = 0; nf < 8; nf++)
#pragma unroll
        for (int e = 0; e < 4; e++) o[nf][e] = 0.f;
    float lacc[4] = {0.f, 0.f, 0.f, 0.f};
    float mA = -1e30f, mB = -1e30f;

    const uint32_t one2 = 0x3C003C00u;
    uint32_t bones[2] = { one2, one2 };

    const int nTiles = it + 1;
    const int rowMin = m0 + wid * 16;

    for (int ti = 0; ti < nTiles; ti++) {
        int s0 = ti * 64;
        if (ti > 0) { CP_WAIT(0); __syncthreads(); }
        if (ti + 1 < nTiles) { loadTile((ti + 1) & 1, s0 + 64); CP_COMMIT(); }

        if (s0 <= rowMin + 15) {
            uint32_t kB = ksB + (uint32_t)((ti & 1) * 64 * HST) * 2u;
            uint32_t vB = vsB + (uint32_t)((ti & 1) * 64 * HST) * 2u;

            // Diagonal tile for this warp's strip? (only possible at s0 == m0)
            bool diag = (s0 + 63 > rowMin);
            int blkMax = diag ? (wid + 1) : 4;   // warp-uniform

            float s[8][4];
#pragma unroll
            for (int nf = 0; nf < 8; nf++)
#pragma unroll
                for (int e = 0; e < 4; e++) s[nf][e] = 0.f;
#pragma unroll
            for (int kf = 0; kf < 4; kf++) {
#pragma unroll
                for (int nfp = 0; nfp < 4; nfp++) {
                    if (nfp < blkMax) {
                        uint32_t r4[4];
                        ldsm_x4(kB + ((nfp * 16 + bRow) * HST + kf * 16 + bColH) * 2u, r4);
                        uint32_t bf0[2] = { r4[0], r4[1] };
                        uint32_t bf1[2] = { r4[2], r4[3] };
                        mma_f16(s[2 * nfp], qf[kf], bf0);
                        mma_f16(s[2 * nfp + 1], qf[kf], bf1);
                    }
                }
            }

            if (diag) {
                // fully-masked blocks -> -inf (their P becomes exactly 0)
#pragma unroll
                for (int nf = 0; nf < 8; nf++) {
                    if ((nf >> 1) >= blkMax) {
                        s[nf][0] = -1e30f; s[nf][1] = -1e30f;
                        s[nf][2] = -1e30f; s[nf][3] = -1e30f;
                    }
                }
                // partial block: nfp == wid -> nf in {2wid, 2wid+1}
                int ra = rowMin + g, rb = ra + 8;
#pragma unroll
                for (int nf = 0; nf < 8; nf++) {
                    if ((nf >> 1) == wid) {
                        int c0 = s0 + nf * 8 + 2 * t, c1 = c0 + 1;
                        if (c0 > ra) s[nf][0] = -1e30f;
                        if (c1 > ra) s[nf][1] = -1e30f;
                        if (c0 > rb) s[nf][2] = -1e30f;
                        if (c1 > rb) s[nf][3] = -1e30f;
                    }
                }
            }

            float mtA = -1e30f, mtB = -1e30f;
#pragma unroll
            for (int nf = 0; nf < 8; nf++) {
                mtA = fmaxf(mtA, fmaxf(s[nf][0], s[nf][1]));
                mtB = fmaxf(mtB, fmaxf(s[nf][2], s[nf][3]));
            }
            mtA = fmaxf(mtA, __shfl_xor_sync(0xffffffffu, mtA, 1));
            mtA = fmaxf(mtA, __shfl_xor_sync(0xffffffffu, mtA, 2));
            mtB = fmaxf(mtB, __shfl_xor_sync(0xffffffffu, mtB, 1));
            mtB = fmaxf(mtB, __shfl_xor_sync(0xffffffffu, mtB, 2));
            float mnA = fmaxf(mA, mtA), mnB = fmaxf(mB, mtB);

            bool nochg = (mnA == mA) & (mnB == mB);
            if (!__all_sync(0xffffffffu, nochg)) {
                float aAl = ex2f(mA - mnA), aBl = ex2f(mB - mnB);
#pragma unroll
                for (int nf = 0; nf < 8; nf++) {
                    o[nf][0] *= aAl; o[nf][1] *= aAl;
                    o[nf][2] *= aBl; o[nf][3] *= aBl;
                }
                lacc[0] *= aAl; lacc[1] *= aAl;
                lacc[2] *= aBl; lacc[3] *= aBl;
            }
            mA = mnA; mB = mnB;

            uint32_t pf[4][4];
#pragma unroll
            for (int nf = 0; nf < 8; nf++) {
                if ((nf >> 1) < blkMax) {
                    __half2 dA = __floats2half2_rn(s[nf][0] - mnA, s[nf][1] - mnA);
                    __half2 dB = __floats2half2_rn(s[nf][2] - mnB, s[nf][3] - mnB);
                    pf[nf >> 1][(nf & 1) * 2]     = h2ex2(*(uint32_t*)&dA);
                    pf[nf >> 1][(nf & 1) * 2 + 1] = h2ex2(*(uint32_t*)&dB);
                }
            }

#pragma unroll
            for (int kf = 0; kf < 4; kf++) {
                if (kf < blkMax) {
                    mma_f16(lacc, pf[kf], bones);
#pragma unroll
                    for (int nfp = 0; nfp < 4; nfp++) {
                        uint32_t r4[4];
                        ldsm_x4t(vB + ((kf * 16 + vRow) * HST + nfp * 16 + vColH) * 2u, r4);
                        uint32_t bf0[2] = { r4[0], r4[1] };
                        uint32_t bf1[2] = { r4[2], r4[3] };
                        mma_f16(o[2 * nfp], pf[kf], bf0);
                        mma_f16(o[2 * nfp + 1], pf[kf], bf1);
                    }
                }
            }
        }
    }

    float iA = 1.f / lacc[0], iB = 1.f / lacc[2];
    int rA = m0 + wid * 16 + g;
    __half* y0 = yh + (size_t)(b * T_ + rA) * D_ + h * DH_;
    __half* y1 = yh + (size_t)(b * T_ + rA + 8) * D_ + h * DH_;
#pragma unroll
    for (int nf = 0; nf < 8; nf++) {
        int c = nf * 8 + 2 * t;
        *(__half2*)(y0 + c) = __floats2half2_rn(o[nf][0] * iA, o[nf][1] * iA);
        *(__half2*)(y1 + c) = __floats2half2_rn(o[nf][2] * iB, o[nf][3] * iB);
    }
}

// ---------------------------------------------------------------------------
// Launch
// ---------------------------------------------------------------------------
extern "C" void kernel_launch(void* const* d_in, const int* in_sizes, int n_in,
                              void* d_out, int out_size) {
    const float* x     = (const float*)d_in[0];
    const float* Wqkv  = (const float*)d_in[1];
    const float* bqkv  = (const float*)d_in[2];
    const float* Wproj = (const float*)d_in[3];
    const float* bproj = (const float*)d_in[4];
    float* out = (float*)d_out;

    __half *xh, *wqkvh, *wprojh, *yh, *qkvh;
    cudaGetSymbolAddress((void**)&xh, g_xh);
    cudaGetSymbolAddress((void**)&wqkvh, g_wqkvh);
    cudaGetSymbolAddress((void**)&wprojh, g_wprojh);
    cudaGetSymbolAddress((void**)&yh, g_yh);
    cudaGetSymbolAddress((void**)&qkvh, g_qkvh);

    // 0) single merged fp16 rounding pre-pass
    {
        int total = N1H + N2H + N3H;
        round3_kernel<<<(total + 255) / 256, 256>>>(x, xh, Wqkv, wqkvh, Wproj, wprojh);
    }

    int gemm_smem = NSTG * STGH * (int)sizeof(__half); // 81920 B
    cudaFuncSetAttribute(gemm_f16<0>,
                         cudaFuncAttributeMaxDynamicSharedMemorySize, gemm_smem);
    cudaFuncSetAttribute(gemm_f16<1>,
                         cudaFuncAttributeMaxDynamicSharedMemorySize, gemm_smem);

    // 1) QKV GEMM + fused rope -> fp16 qkvh (natural layout)
    {
        dim3 grid(QKV_COLS / 128, BT_ / 128);
        gemm_f16<1><<<grid, 128, gemm_smem>>>(xh, wqkvh, bqkv, nullptr,
                                              qkvh, BT_, QKV_COLS, D_);
    }

    // 2) Flash attention (fp16 mma), Br=64, occupancy-4 CTAs, diagonal skip
    {
        int smem = (MT_ * HST + 4 * 64 * HST) * (int)sizeof(__half); // 46080 B
        cudaFuncSetAttribute(attn_f16_kernel,
                             cudaFuncAttributeMaxDynamicSharedMemorySize, smem);
        dim3 grid(T_ / MT_, B_ * H_);
        attn_f16_kernel<<<grid, 128, smem>>>(qkvh, yh);
    }

    // 3) Proj GEMM (fp16 mma) -> fp32 out
    {
        dim3 grid(D_ / 128, BT_ / 128);
        gemm_f16<0><<<grid, 128, gemm_smem>>>(yh, wprojh, bproj, out,
                                              nullptr, BT_, D_, D_);
    }
}

// round 16
// speedup vs baseline: 1.0719x; 1.0719x over previous
#include <cuda_runtime.h>
#include <cuda_fp16.h>
#include <math.h>
#include <stdint.h>

#define B_  2
#define T_  2048
#define D_  1024
#define H_  16
#define DH_ 64
#define QKV_COLS 3072   // 3*D
#define BT_ (B_*T_)     // 4096

// Scratch (allocation-free rule: __device__ globals)
__device__ __half g_xh[(size_t)BT_ * D_];            // 8 MB
__device__ __half g_wqkvh[(size_t)QKV_COLS * D_];    // 6 MB
__device__ __half g_wprojh[(size_t)D_ * D_];         // 2 MB
__device__ __half g_yh[(size_t)BT_ * D_];            // 8 MB
__device__ __half g_qkvh[(size_t)BT_ * QKV_COLS];    // 24 MB (rope applied, q scaled)

// ---------------------------------------------------------------------------
// Helpers
// ---------------------------------------------------------------------------
__device__ __forceinline__ float ex2f(float x) {
    float r;
    asm("ex2.approx.f32 %0, %1;" : "=f"(r) : "f"(x));
    return r;
}
__device__ __forceinline__ uint32_t h2ex2(uint32_t x) {
    uint32_t r;
    asm("ex2.approx.f16x2 %0, %1;" : "=r"(r) : "r"(x));
    return r;
}
__device__ __forceinline__ void mma_f16(float* c, const uint32_t* a, const uint32_t* b) {
    asm volatile(
        "mma.sync.aligned.m16n8k16.row.col.f32.f16.f16.f32 "
        "{%0,%1,%2,%3}, {%4,%5,%6,%7}, {%8,%9}, {%0,%1,%2,%3};"
        : "+f"(c[0]), "+f"(c[1]), "+f"(c[2]), "+f"(c[3])
        : "r"(a[0]), "r"(a[1]), "r"(a[2]), "r"(a[3]), "r"(b[0]), "r"(b[1]));
}
__device__ __forceinline__ void ldsm_x4(uint32_t addr, uint32_t* r) {
    asm volatile("ldmatrix.sync.aligned.m8n8.x4.shared.b16 {%0,%1,%2,%3}, [%4];"
                 : "=r"(r[0]), "=r"(r[1]), "=r"(r[2]), "=r"(r[3]) : "r"(addr));
}
__device__ __forceinline__ void ldsm_x4t(uint32_t addr, uint32_t* r) {
    asm volatile("ldmatrix.sync.aligned.m8n8.x4.trans.shared.b16 {%0,%1,%2,%3}, [%4];"
                 : "=r"(r[0]), "=r"(r[1]), "=r"(r[2]), "=r"(r[3]) : "r"(addr));
}
__device__ __forceinline__ void cpa16(void* smem, const void* g) {
    uint32_t s = (uint32_t)__cvta_generic_to_shared(smem);
    asm volatile("cp.async.cg.shared.global [%0], [%1], 16;" :: "r"(s), "l"(g));
}
#define CP_COMMIT() asm volatile("cp.async.commit_group;")
#define CP_WAIT(n)  asm volatile("cp.async.wait_group %0;" :: "n"(n))

// ---------------------------------------------------------------------------
// Merged fp16 rounding pre-pass (x, Wqkv, Wproj in one launch)
// ---------------------------------------------------------------------------
#define N1H (BT_*D_/2)
#define N2H (QKV_COLS*D_/2)
#define N3H (D_*D_/2)
__global__ void round3_kernel(const float* __restrict__ x, __half* __restrict__ xh,
                              const float* __restrict__ wq, __half* __restrict__ wqh,
                              const float* __restrict__ wp, __half* __restrict__ wph) {
    int i = blockIdx.x * blockDim.x + threadIdx.x;
    if (i < N1H) {
        float2 v = ((const float2*)x)[i];
        ((__half2*)xh)[i] = __floats2half2_rn(v.x, v.y);
    } else if (i < N1H + N2H) {
        int j = i - N1H;
        float2 v = ((const float2*)wq)[j];
        ((__half2*)wqh)[j] = __floats2half2_rn(v.x, v.y);
    } else if (i < N1H + N2H + N3H) {
        int j = i - N1H - N2H;
        float2 v = ((const float2*)wp)[j];
        ((__half2*)wph)[j] = __floats2half2_rn(v.x, v.y);
    }
}

// ---------------------------------------------------------------------------
// fp16 tensor-core GEMM (NT): 4 warps (2x2), warp tile 64x64, CTA 128x128,
// BK=32 halves, 4-stage cp.async ring, ldmatrix frags, m16n8k16 mma.
// EPI=0: C = acc + bias (fp32).
// EPI=1: fused rope -> fp16 qkvh in GEMM-natural layout (coalesced stores).
// ---------------------------------------------------------------------------
#define GSH 40                 // smem row stride in halves (32 + 8 pad)
#define STGH (2*128*GSH)       // halves per stage (A tile + B tile)
#define NSTG 4

template <int EPI>
__global__ __launch_bounds__(128, 2)
void gemm_f16(const __half* __restrict__ A, const __half* __restrict__ W,
              const float* __restrict__ bias, float* __restrict__ C,
              __half* __restrict__ Ch, int M, int N, int K) {
    extern __shared__ __half hsm[];

    int tid = threadIdx.x, lane = tid & 31, wid = tid >> 5;
    int g = lane >> 2, t = lane & 3;
    int wm = wid >> 1, wn = wid & 1;
    int m0 = blockIdx.y * 128, n0 = blockIdx.x * 128;

    int lr = lane & 7, sel = lane >> 3;
    int aRow = lr + (sel & 1) * 8, aColH = (sel >> 1) * 8;
    int bRow = lr + (sel >> 1) * 8, bColH = (sel & 1) * 8;

    uint32_t smBase = (uint32_t)__cvta_generic_to_shared(hsm);

    float acc[4][8][4];
#pragma unroll
    for (int i = 0; i < 4; i++)
#pragma unroll
        for (int j = 0; j < 8; j++)
#pragma unroll
            for (int e = 0; e < 4; e++) acc[i][j][e] = 0.f;

    const int nk = K / 32;

    auto loadStage = [&](int st, int kt) {
        __half* as = hsm + st * STGH;
        __half* bs = as + 128 * GSH;
        int k0 = kt * 32;
#pragma unroll
        for (int p = 0; p < 4; p++) {
            int idx = tid + p * 128;
            int row = idx >> 2, c8 = (idx & 3) * 8;
            cpa16(as + row * GSH + c8, A + (size_t)(m0 + row) * K + k0 + c8);
            cpa16(bs + row * GSH + c8, W + (size_t)(n0 + row) * K + k0 + c8);
        }
        CP_COMMIT();
    };

    loadStage(0, 0);
    loadStage(1, 1);
    loadStage(2, 2);

    for (int kt = 0; kt < nk; kt++) {
        int rem = nk - kt;
        if (rem > 2) { CP_WAIT(2); } else if (rem == 2) { CP_WAIT(1); } else { CP_WAIT(0); }
        __syncthreads();
        if (kt + 3 < nk) loadStage((kt + 3) & (NSTG - 1), kt + 3);

        int st = kt & (NSTG - 1);
        uint32_t aB = smBase + (uint32_t)(st * STGH) * 2u;
        uint32_t bB = aB + (uint32_t)(128 * GSH) * 2u;
#pragma unroll
        for (int kk = 0; kk < 2; kk++) {
            uint32_t af[4][4], bf[8][2];
#pragma unroll
            for (int mf = 0; mf < 4; mf++)
                ldsm_x4(aB + ((wm * 64 + mf * 16 + aRow) * GSH + kk * 16 + aColH) * 2u, af[mf]);
#pragma unroll
            for (int nfp = 0; nfp < 4; nfp++) {
                uint32_t r4[4];
                ldsm_x4(bB + ((wn * 64 + nfp * 16 + bRow) * GSH + kk * 16 + bColH) * 2u, r4);
                bf[2 * nfp][0] = r4[0]; bf[2 * nfp][1] = r4[1];
                bf[2 * nfp + 1][0] = r4[2]; bf[2 * nfp + 1][1] = r4[3];
            }
#pragma unroll
            for (int mf = 0; mf < 4; mf++)
#pragma unroll
                for (int nf = 0; nf < 8; nf++)
                    mma_f16(acc[mf][nf], af[mf], bf[nf]);
        }
    }

    if (EPI == 0) {
#pragma unroll
        for (int mf = 0; mf < 4; mf++) {
            int r0 = m0 + wm * 64 + mf * 16 + g;
            int r1 = r0 + 8;
#pragma unroll
            for (int nf = 0; nf < 8; nf++) {
                int c = n0 + wn * 64 + nf * 8 + 2 * t;
                float bx = bias[c], by = bias[c + 1];
                float2 v0 = make_float2(acc[mf][nf][0] + bx, acc[mf][nf][1] + by);
                float2 v1 = make_float2(acc[mf][nf][2] + bx, acc[mf][nf][3] + by);
                *(float2*)(C + (size_t)r0 * N + c) = v0;
                *(float2*)(C + (size_t)r1 * N + c) = v1;
            }
        }
    } else {
        const float QSC = 0.125f * 1.44269504f;
        const float L2_10K = 13.2877123795f;
        int sub[8];
        float invf[8], bx[8], by[8];
#pragma unroll
        for (int nf = 0; nf < 8; nf++) {
            int n = n0 + wn * 64 + nf * 8 + 2 * t;
            int r = n % 192;
            sub[nf] = r >> 6;
            int d = r & 63;
            invf[nf] = ex2f(-((float)(d & ~1) / 64.f) * L2_10K);
            bx[nf] = bias[n];
            by[nf] = bias[n + 1];
        }
#pragma unroll
        for (int mf = 0; mf < 4; mf++) {
#pragma unroll
            for (int hr = 0; hr < 2; hr++) {
                int row = m0 + wm * 64 + mf * 16 + g + hr * 8;
                int tpos = row & (T_ - 1);
                float ftp = (float)tpos;
                __half* crow = Ch + (size_t)row * N;
#pragma unroll
                for (int nf = 0; nf < 8; nf++) {
                    int c = n0 + wn * 64 + nf * 8 + 2 * t;
                    float e = acc[mf][nf][hr * 2]     + bx[nf];
                    float o = acc[mf][nf][hr * 2 + 1] + by[nf];
                    if (sub[nf] == 2) {
                        *(__half2*)(crow + c) = __floats2half2_rn(e, o);
                    } else {
                        float sn, cs;
                        __sincosf(ftp * invf[nf], &sn, &cs);
                        float re = e * cs - o * (1.f - cs);
                        float ro = o * sn + e * (1.f - sn);
                        if (sub[nf] == 0) { re *= QSC; ro *= QSC; }
                        *(__half2*)(crow + c) = __floats2half2_rn(re, ro);
                    }
                }
            }
        }
    }
}

// ---------------------------------------------------------------------------
// Flash attention, fp16 mma. Br=64, 128 threads (4 warps), occupancy 4.
// R16: diagonal tile PEELED out of the mainloop. Mainloop tiles have no
// masking and no bounds check (provably full); the peeled diagonal body
// carries the warp-uniform block skip (blkMax = wid+1).
// ---------------------------------------------------------------------------
#define HST 72   // half-stride per smem row (64 + 8 pad)
#define MT_ 64   // query rows per CTA

__global__ __launch_bounds__(128, 4)
void attn_f16_kernel(const __half* __restrict__ qkv, __half* __restrict__ yh) {
    int bh = blockIdx.y;
    int b = bh >> 4, h = bh & 15;
    int it = gridDim.x - 1 - blockIdx.x;   // heaviest tiles first
    int m0 = it * MT_;
    int tid = threadIdx.x, lane = tid & 31, wid = tid >> 5;
    int g = lane >> 2, t = lane & 3;

    extern __shared__ __half hsm[];
    __half* Qs = hsm;                    // [64][HST]
    __half* Ks = hsm + MT_ * HST;        // [2][64][HST]
    __half* Vs = Ks + 2 * 64 * HST;      // [2][64][HST]
    uint32_t qsB = (uint32_t)__cvta_generic_to_shared(Qs);
    uint32_t ksB = (uint32_t)__cvta_generic_to_shared(Ks);
    uint32_t vsB = (uint32_t)__cvta_generic_to_shared(Vs);

    int lr = lane & 7, sel = lane >> 3;
    int aRow = lr + (sel & 1) * 8, aColH = (sel >> 1) * 8;
    int bRow = lr + (sel >> 1) * 8, bColH = (sel & 1) * 8;
    int vRow = lr + (sel & 1) * 8, vColH = (sel >> 1) * 8;

    // base of this (b, h): row stride QKV_COLS; q at +0, k at +64, v at +128
    const __half* base = qkv + (size_t)(b * T_) * QKV_COLS + h * 192;

    // Q tile: 64 rows x 8 chunks = 512 chunks, 128 threads -> 4 each
#pragma unroll
    for (int p = 0; p < 4; p++) {
        int j = tid + p * 128;
        int row = j >> 3, c8 = (j & 7) * 8;
        cpa16(Qs + row * HST + c8, base + (size_t)(m0 + row) * QKV_COLS + c8);
    }
    auto loadTile = [&](int buf, int s0) {
#pragma unroll
        for (int p = 0; p < 4; p++) {
            int j = tid + p * 128;
            int row = j >> 3, c8 = (j & 7) * 8;
            const __half* src = base + (size_t)(s0 + row) * QKV_COLS;
            cpa16(Ks + buf * 64 * HST + row * HST + c8, src + 64 + c8);
            cpa16(Vs + buf * 64 * HST + row * HST + c8, src + 128 + c8);
        }
    };
    loadTile(0, 0);
    CP_COMMIT();
    CP_WAIT(0);
    __syncthreads();

    uint32_t qf[4][4];
#pragma unroll
    for (int kf = 0; kf < 4; kf++)
        ldsm_x4(qsB + ((wid * 16 + aRow) * HST + kf * 16 + aColH) * 2u, qf[kf]);

    float o[8][4];
#pragma unroll
    for (int nf = 0; nf < 8; nf++)
#pragma unroll
        for (int e = 0; e < 4; e++) o[nf][e] = 0.f;
    float lacc[4] = {0.f, 0.f, 0.f, 0.f};
    float mA = -1e30f, mB = -1e30f;

    const uint32_t one2 = 0x3C003C00u;
    uint32_t bones[2] = { one2, one2 };

    const int nTiles = it + 1;

    // ---------------- mainloop: full (non-diagonal) tiles ----------------
    for (int ti = 0; ti < nTiles - 1; ti++) {
        if (ti > 0) { CP_WAIT(0); __syncthreads(); }
        loadTile((ti + 1) & 1, (ti + 1) * 64);   // always a next tile here
        CP_COMMIT();

        uint32_t kB = ksB + (uint32_t)((ti & 1) * 64 * HST) * 2u;
        uint32_t vB = vsB + (uint32_t)((ti & 1) * 64 * HST) * 2u;

        float s[8][4];
#pragma unroll
        for (int nf = 0; nf < 8; nf++)
#pragma unroll
            for (int e = 0; e < 4; e++) s[nf][e] = 0.f;
#pragma unroll
        for (int kf = 0; kf < 4; kf++) {
#pragma unroll
            for (int nfp = 0; nfp < 4; nfp++) {
                uint32_t r4[4];
                ldsm_x4(kB + ((nfp * 16 + bRow) * HST + kf * 16 + bColH) * 2u, r4);
                uint32_t bf0[2] = { r4[0], r4[1] };
                uint32_t bf1[2] = { r4[2], r4[3] };
                mma_f16(s[2 * nfp], qf[kf], bf0);
                mma_f16(s[2 * nfp + 1], qf[kf], bf1);
            }
        }

        float mtA = -1e30f, mtB = -1e30f;
#pragma unroll
        for (int nf = 0; nf < 8; nf++) {
            mtA = fmaxf(mtA, fmaxf(s[nf][0], s[nf][1]));
            mtB = fmaxf(mtB, fmaxf(s[nf][2], s[nf][3]));
        }
        mtA = fmaxf(mtA, __shfl_xor_sync(0xffffffffu, mtA, 1));
        mtA = fmaxf(mtA, __shfl_xor_sync(0xffffffffu, mtA, 2));
        mtB = fmaxf(mtB, __shfl_xor_sync(0xffffffffu, mtB, 1));
        mtB = fmaxf(mtB, __shfl_xor_sync(0xffffffffu, mtB, 2));
        float mnA = fmaxf(mA, mtA), mnB = fmaxf(mB, mtB);

        bool nochg = (mnA == mA) & (mnB == mB);
        if (!__all_sync(0xffffffffu, nochg)) {
            float aAl = ex2f(mA - mnA), aBl = ex2f(mB - mnB);
#pragma unroll
            for (int nf = 0; nf < 8; nf++) {
                o[nf][0] *= aAl; o[nf][1] *= aAl;
                o[nf][2] *= aBl; o[nf][3] *= aBl;
            }
            lacc[0] *= aAl; lacc[1] *= aAl;
            lacc[2] *= aBl; lacc[3] *= aBl;
        }
        mA = mnA; mB = mnB;

        uint32_t pf[4][4];
#pragma unroll
        for (int nf = 0; nf < 8; nf++) {
            __half2 dA = __floats2half2_rn(s[nf][0] - mnA, s[nf][1] - mnA);
            __half2 dB = __floats2half2_rn(s[nf][2] - mnB, s[nf][3] - mnB);
            pf[nf >> 1][(nf & 1) * 2]     = h2ex2(*(uint32_t*)&dA);
            pf[nf >> 1][(nf & 1) * 2 + 1] = h2ex2(*(uint32_t*)&dB);
        }

#pragma unroll
        for (int kf = 0; kf < 4; kf++) {
            mma_f16(lacc, pf[kf], bones);
#pragma unroll
            for (int nfp = 0; nfp < 4; nfp++) {
                uint32_t r4[4];
                ldsm_x4t(vB + ((kf * 16 + vRow) * HST + nfp * 16 + vColH) * 2u, r4);
                uint32_t bf0[2] = { r4[0], r4[1] };
                uint32_t bf1[2] = { r4[2], r4[3] };
                mma_f16(o[2 * nfp], pf[kf], bf0);
                mma_f16(o[2 * nfp + 1], pf[kf], bf1);
            }
        }
    }

    // ---------------- peeled diagonal tile (ti = nTiles-1) ----------------
    {
        int ti = nTiles - 1;
        int s0 = ti * 64;
        if (ti > 0) { CP_WAIT(0); __syncthreads(); }

        uint32_t kB = ksB + (uint32_t)((ti & 1) * 64 * HST) * 2u;
        uint32_t vB = vsB + (uint32_t)((ti & 1) * 64 * HST) * 2u;

        const int blkMax = wid + 1;            // warp-uniform
        const int rowMin = m0 + wid * 16;

        float s[8][4];
#pragma unroll
        for (int nf = 0; nf < 8; nf++)
#pragma unroll
            for (int e = 0; e < 4; e++) s[nf][e] = -1e30f;
#pragma unroll
        for (int nf = 0; nf < 8; nf++)
            if ((nf >> 1) < blkMax)
#pragma unroll
                for (int e = 0; e < 4; e++) s[nf][e] = 0.f;

#pragma unroll
        for (int kf = 0; kf < 4; kf++) {
#pragma unroll
            for (int nfp = 0; nfp < 4; nfp++) {
                if (nfp < blkMax) {
                    uint32_t r4[4];
                    ldsm_x4(kB + ((nfp * 16 + bRow) * HST + kf * 16 + bColH) * 2u, r4);
                    uint32_t bf0[2] = { r4[0], r4[1] };
                    uint32_t bf1[2] = { r4[2], r4[3] };
                    mma_f16(s[2 * nfp], qf[kf], bf0);
                    mma_f16(s[2 * nfp + 1], qf[kf], bf1);
                }
            }
        }

        // mask the partial block (nfp == wid)
        {
            int ra = rowMin + g, rb = ra + 8;
#pragma unroll
            for (int nf = 0; nf < 8; nf++) {
                if ((nf >> 1) == wid) {
                    int c0 = s0 + nf * 8 + 2 * t, c1 = c0 + 1;
                    if (c0 > ra) s[nf][0] = -1e30f;
                    if (c1 > ra) s[nf][1] = -1e30f;
                    if (c0 > rb) s[nf][2] = -1e30f;
                    if (c1 > rb) s[nf][3] = -1e30f;
                }
            }
        }

        float mtA = -1e30f, mtB = -1e30f;
#pragma unroll
        for (int nf = 0; nf < 8; nf++) {
            mtA = fmaxf(mtA, fmaxf(s[nf][0], s[nf][1]));
            mtB = fmaxf(mtB, fmaxf(s[nf][2], s[nf][3]));
        }
        mtA = fmaxf(mtA, __shfl_xor_sync(0xffffffffu, mtA, 1));
        mtA = fmaxf(mtA, __shfl_xor_sync(0xffffffffu, mtA, 2));
        mtB = fmaxf(mtB, __shfl_xor_sync(0xffffffffu, mtB, 1));
        mtB = fmaxf(mtB, __shfl_xor_sync(0xffffffffu, mtB, 2));
        float mnA = fmaxf(mA, mtA), mnB = fmaxf(mB, mtB);

        bool nochg = (mnA == mA) & (mnB == mB);
        if (!__all_sync(0xffffffffu, nochg)) {
            float aAl = ex2f(mA - mnA), aBl = ex2f(mB - mnB);
#pragma unroll
            for (int nf = 0; nf < 8; nf++) {
                o[nf][0] *= aAl; o[nf][1] *= aAl;
                o[nf][2] *= aBl; o[nf][3] *= aBl;
            }
            lacc[0] *= aAl; lacc[1] *= aAl;
            lacc[2] *= aBl; lacc[3] *= aBl;
        }

        uint32_t pf[4][4];
#pragma unroll
        for (int nf = 0; nf < 8; nf++) {
            if ((nf >> 1) < blkMax) {
                __half2 dA = __floats2half2_rn(s[nf][0] - mnA, s[nf][1] - mnA);
                __half2 dB = __floats2half2_rn(s[nf][2] - mnB, s[nf][3] - mnB);
                pf[nf >> 1][(nf & 1) * 2]     = h2ex2(*(uint32_t*)&dA);
                pf[nf >> 1][(nf & 1) * 2 + 1] = h2ex2(*(uint32_t*)&dB);
            }
        }

#pragma unroll
        for (int kf = 0; kf < 4; kf++) {
            if (kf < blkMax) {
                mma_f16(lacc, pf[kf], bones);
#pragma unroll
                for (int nfp = 0; nfp < 4; nfp++) {
                    uint32_t r4[4];
                    ldsm_x4t(vB + ((kf * 16 + vRow) * HST + nfp * 16 + vColH) * 2u, r4);
                    uint32_t bf0[2] = { r4[0], r4[1] };
                    uint32_t bf1[2] = { r4[2], r4[3] };
                    mma_f16(o[2 * nfp], pf[kf], bf0);
                    mma_f16(o[2 * nfp + 1], pf[kf], bf1);
                }
            }
        }
    }

    float iA = 1.f / lacc[0], iB = 1.f / lacc[2];
    int rA = m0 + wid * 16 + g;
    __half* y0 = yh + (size_t)(b * T_ + rA) * D_ + h * DH_;
    __half* y1 = yh + (size_t)(b * T_ + rA + 8) * D_ + h * DH_;
#pragma unroll
    for (int nf = 0; nf < 8; nf++) {
        int c = nf * 8 + 2 * t;
        *(__half2*)(y0 + c) = __floats2half2_rn(o[nf][0] * iA, o[nf][1] * iA);
        *(__half2*)(y1 + c) = __floats2half2_rn(o[nf][2] * iB, o[nf][3] * iB);
    }
}

// ---------------------------------------------------------------------------
// Launch
// ---------------------------------------------------------------------------
extern "C" void kernel_launch(void* const* d_in, const int* in_sizes, int n_in,
                              void* d_out, int out_size) {
    const float* x     = (const float*)d_in[0];
    const float* Wqkv  = (const float*)d_in[1];
    const float* bqkv  = (const float*)d_in[2];
    const float* Wproj = (const float*)d_in[3];
    const float* bproj = (const float*)d_in[4];
    float* out = (float*)d_out;

    __half *xh, *wqkvh, *wprojh, *yh, *qkvh;
    cudaGetSymbolAddress((void**)&xh, g_xh);
    cudaGetSymbolAddress((void**)&wqkvh, g_wqkvh);
    cudaGetSymbolAddress((void**)&wprojh, g_wprojh);
    cudaGetSymbolAddress((void**)&yh, g_yh);
    cudaGetSymbolAddress((void**)&qkvh, g_qkvh);

    // 0) single merged fp16 rounding pre-pass
    {
        int total = N1H + N2H + N3H;
        round3_kernel<<<(total + 255) / 256, 256>>>(x, xh, Wqkv, wqkvh, Wproj, wprojh);
    }

    int gemm_smem = NSTG * STGH * (int)sizeof(__half); // 81920 B
    cudaFuncSetAttribute(gemm_f16<0>,
                         cudaFuncAttributeMaxDynamicSharedMemorySize, gemm_smem);
    cudaFuncSetAttribute(gemm_f16<1>,
                         cudaFuncAttributeMaxDynamicSharedMemorySize, gemm_smem);

    // 1) QKV GEMM + fused rope -> fp16 qkvh (natural layout)
    {
        dim3 grid(QKV_COLS / 128, BT_ / 128);
        gemm_f16<1><<<grid, 128, gemm_smem>>>(xh, wqkvh, bqkv, nullptr,
                                              qkvh, BT_, QKV_COLS, D_);
    }

    // 2) Flash attention (fp16 mma), Br=64, occupancy-4 CTAs, peeled diagonal
    {
        int smem = (MT_ * HST + 4 * 64 * HST) * (int)sizeof(__half); // 46080 B
        cudaFuncSetAttribute(attn_f16_kernel,
                             cudaFuncAttributeMaxDynamicSharedMemorySize, smem);
        dim3 grid(T_ / MT_, B_ * H_);
        attn_f16_kernel<<<grid, 128, smem>>>(qkvh, yh);
    }

    // 3) Proj GEMM (fp16 mma) -> fp32 out
    {
        dim3 grid(D_ / 128, BT_ / 128);
        gemm_f16<0><<<grid, 128, gemm_smem>>>(yh, wprojh, bproj, out,
                                              nullptr, BT_, D_, D_);
    }
}